// round 4
// baseline (speedup 1.0000x reference)
#include <cuda_runtime.h>
#include <cstdint>

// Problem constants
#define KDIM     256          // code / centroid dimension
#define NCOLS    40           // NUM_CLASSES * K_CENTROIDS = 10*4
#define NCLASSES 10
#define BM       128          // rows per CTA
#define NTHREADS 256          // 8 warps
#define CHUNK    64           // K chunk width (floats)
#define ASTRIDE  68           // CHUNK + 4 pad -> conflict-free A fragment LDS

// Normalized, transposed, tf32-rounded centroids: [k][n]
__device__ float g_centsT[KDIM * NCOLS];

// ---------------------------------------------------------------------------
// Prep: L2-normalize each of the 40 centroid vectors (matches
// x / max(||x||, 1e-12)), round to tf32, store transposed [K][N].
// ---------------------------------------------------------------------------
__global__ void prep_kernel(const float* __restrict__ cents) {
    const int w = threadIdx.x >> 5;
    const int lane = threadIdx.x & 31;
    for (int v = w; v < NCOLS; v += (int)(blockDim.x >> 5)) {
        const float* src = cents + v * KDIM;
        float vals[8];
        float s = 0.f;
        #pragma unroll
        for (int i = 0; i < 8; i++) {
            vals[i] = src[lane + 32 * i];
            s += vals[i] * vals[i];
        }
        #pragma unroll
        for (int off = 16; off; off >>= 1)
            s += __shfl_xor_sync(0xffffffffu, s, off);
        const float inv = 1.f / fmaxf(sqrtf(s), 1e-12f);
        #pragma unroll
        for (int i = 0; i < 8; i++) {
            float x = vals[i] * inv;
            uint32_t u;
            asm("cvt.rna.tf32.f32 %0, %1;" : "=r"(u) : "f"(x));
            g_centsT[(lane + 32 * i) * NCOLS + v] = __uint_as_float(u);
        }
    }
}

// ---------------------------------------------------------------------------
// Main: GEMM M=nrows, N=40, K=256 with mma.sync m16n8k8 tf32,
// fused max-over-k + (1 - sim) epilogue.
// smem: A double buffer 2*[128][68] f32 + B [256][40] f32 = 110592 B
// ---------------------------------------------------------------------------
extern __shared__ float smem_dyn[];

__global__ void __launch_bounds__(NTHREADS, 2)
gemm_kernel(const float* __restrict__ codes, float* __restrict__ out,
            int nrows) {
    float* const Abuf0 = smem_dyn;
    float* const Abuf1 = smem_dyn + BM * ASTRIDE;
    float* const Bsm   = smem_dyn + 2 * BM * ASTRIDE;

    const int tid = threadIdx.x;
    const long rowbase = (long)blockIdx.x * BM;
    if (rowbase >= nrows) return;

    // Stage normalized centroids (L2-resident) into smem: 2560 float4.
    {
        const float4* src = reinterpret_cast<const float4*>(g_centsT);
        float4* dst = reinterpret_cast<float4*>(Bsm);
        #pragma unroll
        for (int i = 0; i < 10; i++)
            dst[tid + NTHREADS * i] = src[tid + NTHREADS * i];
    }

    float4 st[8];  // staging registers: one 64-wide K chunk of the A tile

    auto load_chunk = [&](int c) {
        #pragma unroll
        for (int i = 0; i < 8; i++) {
            const int f  = tid + NTHREADS * i;   // float4 index in chunk
            const int r  = f >> 4;               // row 0..127 (16 float4/row)
            const int c4 = f & 15;
            long row = rowbase + r;
            if (row >= nrows) row = nrows - 1;   // clamp (dup load, store guarded)
            st[i] = __ldg(reinterpret_cast<const float4*>(
                              codes + row * (long)KDIM + c * CHUNK) + c4);
        }
    };
    auto store_chunk = [&](float* buf) {
        #pragma unroll
        for (int i = 0; i < 8; i++) {
            const int f  = tid + NTHREADS * i;
            const int r  = f >> 4;
            const int c4 = f & 15;
            *reinterpret_cast<float4*>(buf + r * ASTRIDE + c4 * 4) = st[i];
        }
    };

    // Pipeline prologue
    load_chunk(0);
    store_chunk(Abuf0);
    load_chunk(1);
    __syncthreads();

    const int lane = tid & 31;
    const int warp = tid >> 5;
    const int g = lane >> 2;   // 0..7  (row group / n within tile)
    const int q = lane & 3;    // 0..3  (k within group / col pair)

    float acc[5][4];
    #pragma unroll
    for (int n = 0; n < 5; n++)
        #pragma unroll
        for (int j = 0; j < 4; j++) acc[n][j] = 0.f;

    const uint32_t* const bbase =
        reinterpret_cast<const uint32_t*>(Bsm) + q * NCOLS + g;

    #pragma unroll
    for (int c = 0; c < 4; c++) {
        const float* abuf = (c & 1) ? Abuf1 : Abuf0;
        const uint32_t* ab = reinterpret_cast<const uint32_t*>(abuf)
                             + (warp * 16 + g) * ASTRIDE + q;
        #pragma unroll
        for (int kk = 0; kk < CHUNK; kk += 8) {
            const uint32_t a0 = ab[kk];
            const uint32_t a1 = ab[kk + 8 * ASTRIDE];
            const uint32_t a2 = ab[kk + 4];
            const uint32_t a3 = ab[kk + 4 + 8 * ASTRIDE];
            const int kg = c * CHUNK + kk;
            #pragma unroll
            for (int nt = 0; nt < 5; nt++) {
                const uint32_t b0 = bbase[kg * NCOLS + nt * 8];
                const uint32_t b1 = bbase[(kg + 4) * NCOLS + nt * 8];
                asm volatile(
                    "mma.sync.aligned.m16n8k8.row.col.f32.tf32.tf32.f32 "
                    "{%0,%1,%2,%3}, {%4,%5,%6,%7}, {%8,%9}, {%0,%1,%2,%3};"
                    : "+f"(acc[nt][0]), "+f"(acc[nt][1]),
                      "+f"(acc[nt][2]), "+f"(acc[nt][3])
                    : "r"(a0), "r"(a1), "r"(a2), "r"(a3), "r"(b0), "r"(b1));
            }
        }
        __syncthreads();                         // all reads of abuf done
        if (c + 1 < 4) store_chunk((c & 1) ? Abuf0 : Abuf1);  // chunk c+1
        if (c + 2 < 4) load_chunk(c + 2);        // prefetch chunk c+2
        if (c + 1 < 4) __syncthreads();          // STS visible before next MMA
    }

    // Epilogue: per n8 tile -> 2 classes (4 k-centroids each).
    // Thread q holds cols {2q, 2q+1}; lanes q^1 pair up to cover 4 cols.
    const long r0 = rowbase + warp * 16 + g;
    const long r1 = r0 + 8;
    #pragma unroll
    for (int nt = 0; nt < 5; nt++) {
        float m0 = fmaxf(acc[nt][0], acc[nt][1]);   // row r0
        float m1 = fmaxf(acc[nt][2], acc[nt][3]);   // row r1
        m0 = fmaxf(m0, __shfl_xor_sync(0xffffffffu, m0, 1));
        m1 = fmaxf(m1, __shfl_xor_sync(0xffffffffu, m1, 1));
        const int cls = nt * 2 + (q >> 1);
        if ((q & 1) == 0) {
            if (r0 < nrows) out[r0 * NCLASSES + cls] = 1.f - m0;
            if (r1 < nrows) out[r1 * NCLASSES + cls] = 1.f - m1;
        }
    }
}

// ---------------------------------------------------------------------------
extern "C" void kernel_launch(void* const* d_in, const int* in_sizes, int n_in,
                              void* d_out, int out_size) {
    const float* codes = (const float*)d_in[0];      // (B, 256) f32
    const float* cents = (const float*)d_in[1];      // (10, 4, 256) f32
    float* out = (float*)d_out;                      // (B, 10) f32

    const int nrows = in_sizes[0] / KDIM;
    const int smem_bytes = (2 * BM * ASTRIDE + KDIM * NCOLS) * (int)sizeof(float);

    cudaFuncSetAttribute(gemm_kernel,
                         cudaFuncAttributeMaxDynamicSharedMemorySize,
                         smem_bytes);

    prep_kernel<<<1, 256>>>(cents);

    const int blocks = (nrows + BM - 1) / BM;
    gemm_kernel<<<blocks, NTHREADS, smem_bytes>>>(codes, out, nrows);
}

// round 5
// speedup vs baseline: 1.5555x; 1.5555x over previous
#include <cuda_runtime.h>
#include <cstdint>

#define KDIM     256
#define NCOLS    40          // 10 classes * 4 centroids
#define NCLASSES 10
#define BM       256         // rows per CTA: 8 warps x 32 rows
#define NTHREADS 256
#define NCHUNK   8           // 8 chunks of K=32

// Pre-scattered, normalized, tf32-rounded B fragments.
// Layout: float4 index = ((c*5 + nt)*2 + i)*32 + lane
//   holding B_nat[n = nt*8 + g][k = c*32 + 8q + 4i .. +3],  lane = g*4+q
__device__ float4 g_Bfrag[NCHUNK * 5 * 2 * 32];

// ---------------------------------------------------------------------------
// Prep: normalize 40 centroid vectors (x / max(||x||,1e-12)), tf32-round,
// scatter into the per-lane fragment layout above.
// ---------------------------------------------------------------------------
__global__ void prep_kernel(const float* __restrict__ cents) {
    const int w    = threadIdx.x >> 5;
    const int lane = threadIdx.x & 31;
    float* Bf = reinterpret_cast<float*>(g_Bfrag);
    for (int v = w; v < NCOLS; v += (int)(blockDim.x >> 5)) {
        const float* src = cents + v * KDIM;
        float vals[8];
        float s = 0.f;
        #pragma unroll
        for (int i = 0; i < 8; i++) {
            vals[i] = src[lane + 32 * i];
            s += vals[i] * vals[i];
        }
        #pragma unroll
        for (int off = 16; off; off >>= 1)
            s += __shfl_xor_sync(0xffffffffu, s, off);
        const float inv = 1.f / fmaxf(sqrtf(s), 1e-12f);
        const int nt = v >> 3;
        const int g  = v & 7;
        #pragma unroll
        for (int i = 0; i < 8; i++) {
            const int k = lane + 32 * i;
            float x = vals[i] * inv;
            uint32_t u;
            asm("cvt.rna.tf32.f32 %0, %1;" : "=r"(u) : "f"(x));
            const int c   = k >> 5;
            const int w32 = k & 31;
            const int q   = w32 >> 3;
            const int ii  = (w32 >> 2) & 1;
            const int f   = w32 & 3;
            Bf[((((c * 5 + nt) * 2 + ii) * 32) + (g * 4 + q)) * 4 + f] =
                __uint_as_float(u);
        }
    }
}

// ---------------------------------------------------------------------------
// Main: GEMM M=nrows, N=40, K=256, mma m16n8k8 tf32.
// A: direct global->register LDG.128 (k-permuted slot mapping, no smem).
// B: conflict-free LDS.128 fragments from smem (staged once per CTA).
// Fused epilogue: per class, 1 - max over 4 centroids.
// ---------------------------------------------------------------------------
__global__ void __launch_bounds__(NTHREADS, 2)
gemm_kernel(const float* __restrict__ codes, float* __restrict__ out,
            int nrows) {
    __shared__ float4 Bsm[NCHUNK * 5 * 2 * 32];   // 40 KB

    const int tid = threadIdx.x;
    const long rowbase = (long)blockIdx.x * BM;

    // Stage B fragments (tiny, L2-resident)
    #pragma unroll
    for (int i = 0; i < 10; i++)
        Bsm[tid + NTHREADS * i] = g_Bfrag[tid + NTHREADS * i];
    __syncthreads();

    const int lane = tid & 31;
    const int warp = tid >> 5;
    const int g = lane >> 2;     // 0..7
    const int q = lane & 3;      // 0..3

    // 4 rows per thread: j=0,1 -> m-tile 0 (rows g, g+8); j=2,3 -> tile 1.
    long rrow[4];
    const float* aptr[4];
    #pragma unroll
    for (int j = 0; j < 4; j++) {
        rrow[j] = rowbase + warp * 32 + g + 8 * j;
        long rc = rrow[j] < nrows ? rrow[j] : (long)(nrows - 1);
        aptr[j] = codes + rc * KDIM + 8 * q;   // thread owns cols 8q..8q+7
    }

    float acc[2][5][4];
    #pragma unroll
    for (int t = 0; t < 2; t++)
        #pragma unroll
        for (int n = 0; n < 5; n++)
            #pragma unroll
            for (int j = 0; j < 4; j++) acc[t][n][j] = 0.f;

    #pragma unroll
    for (int c = 0; c < NCHUNK; c++) {
        // A: 8x LDG.128, streaming (no reuse)
        float av[4][8];
        #pragma unroll
        for (int j = 0; j < 4; j++) {
            float4 v0 = __ldcs(reinterpret_cast<const float4*>(aptr[j] + c * 32));
            float4 v1 = __ldcs(reinterpret_cast<const float4*>(aptr[j] + c * 32 + 4));
            av[j][0] = v0.x; av[j][1] = v0.y; av[j][2] = v0.z; av[j][3] = v0.w;
            av[j][4] = v1.x; av[j][5] = v1.y; av[j][6] = v1.z; av[j][7] = v1.w;
        }
        #pragma unroll
        for (int nt = 0; nt < 5; nt++) {
            const float4 wb0 = Bsm[((c * 5 + nt) * 2 + 0) * 32 + lane];
            const float4 wb1 = Bsm[((c * 5 + nt) * 2 + 1) * 32 + lane];
            const float wv[8] = {wb0.x, wb0.y, wb0.z, wb0.w,
                                 wb1.x, wb1.y, wb1.z, wb1.w};
            #pragma unroll
            for (int m = 0; m < 4; m++) {
                const uint32_t b0 = __float_as_uint(wv[2 * m]);
                const uint32_t b1 = __float_as_uint(wv[2 * m + 1]);
                #pragma unroll
                for (int t = 0; t < 2; t++) {
                    const uint32_t a0 = __float_as_uint(av[2 * t][2 * m]);
                    const uint32_t a1 = __float_as_uint(av[2 * t + 1][2 * m]);
                    const uint32_t a2 = __float_as_uint(av[2 * t][2 * m + 1]);
                    const uint32_t a3 = __float_as_uint(av[2 * t + 1][2 * m + 1]);
                    asm volatile(
                        "mma.sync.aligned.m16n8k8.row.col.f32.tf32.tf32.f32 "
                        "{%0,%1,%2,%3}, {%4,%5,%6,%7}, {%8,%9}, {%0,%1,%2,%3};"
                        : "+f"(acc[t][nt][0]), "+f"(acc[t][nt][1]),
                          "+f"(acc[t][nt][2]), "+f"(acc[t][nt][3])
                        : "r"(a0), "r"(a1), "r"(a2), "r"(a3),
                          "r"(b0), "r"(b1));
                }
            }
        }
    }

    // Epilogue: cols {2q,2q+1}; lanes q^1 pair to cover the 4 k-centroids.
    #pragma unroll
    for (int t = 0; t < 2; t++) {
        #pragma unroll
        for (int nt = 0; nt < 5; nt++) {
            float m0 = fmaxf(acc[t][nt][0], acc[t][nt][1]);  // row j=2t
            float m1 = fmaxf(acc[t][nt][2], acc[t][nt][3]);  // row j=2t+1
            m0 = fmaxf(m0, __shfl_xor_sync(0xffffffffu, m0, 1));
            m1 = fmaxf(m1, __shfl_xor_sync(0xffffffffu, m1, 1));
            const int cls = nt * 2 + (q >> 1);
            if ((q & 1) == 0) {
                if (rrow[2 * t] < nrows)
                    out[rrow[2 * t] * NCLASSES + cls] = 1.f - m0;
                if (rrow[2 * t + 1] < nrows)
                    out[rrow[2 * t + 1] * NCLASSES + cls] = 1.f - m1;
            }
        }
    }
}

// ---------------------------------------------------------------------------
extern "C" void kernel_launch(void* const* d_in, const int* in_sizes, int n_in,
                              void* d_out, int out_size) {
    const float* codes = (const float*)d_in[0];   // (B, 256) f32
    const float* cents = (const float*)d_in[1];   // (10, 4, 256) f32
    float* out = (float*)d_out;                   // (B, 10) f32

    const int nrows = in_sizes[0] / KDIM;

    prep_kernel<<<1, 256>>>(cents);

    const int blocks = (nrows + BM - 1) / BM;
    gemm_kernel<<<blocks, NTHREADS>>>(codes, out, nrows);
}